// round 9
// baseline (speedup 1.0000x reference)
#include <cuda_runtime.h>
#include <cuda_fp16.h>

// Problem constants
#define B_ 4
#define H_ 192
#define W_ 640
#define C_ 32
#define S_ 32

#define Wp_   (W_ + 2)                 // padded width
#define ROWB  (Wp_ * 64)               // bytes per row in fp16 scratch (64B/pixel)
#define COPYB (B_ * H_ * ROWB)         // bytes per parity copy

// Two parity-shifted fp16 copies of x: for base column ib, one aligned 128B
// region holds [ x[ib] | x[ib+1] ].
#define COPY_CHUNKS (B_ * H_ * Wp_ * 4)
#define XS_CHUNKS   (2 * COPY_CHUNKS + Wp_ * 4)
__device__ uint4 d_xs[XS_CHUNKS];

// w-table: per (b,s,col,w): { byte-offset (incl. parity-copy base), weight fp32 }
struct __align__(8) WTab2 { int off; float w; };
__device__ WTab2 d_wt2[B_ * S_ * 2 * W_];
// h-table: per (b,s,h): { row0 byte base, row1 byte base, h0 fp32, h1 fp32 }
struct __align__(16) HTab { int r0, r1; float h0, h1; };
__device__ HTab d_ht[B_ * S_ * H_];

#define TAB_THREADS (B_ * S_ * (W_ + H_))
#define TAB_BLOCKS  ((TAB_THREADS + 255) / 256)
#define CONV_THREADS (B_ * H_ * Wp_ * 4)
#define CONV_BLOCKS  ((CONV_THREADS + 255) / 256)

// ---------------------------------------------------------------------------
// Fused prep kernel: table build + fp16 conversion (x read once).
// ---------------------------------------------------------------------------
__global__ void prep_kernel(const float4* __restrict__ x4,
                            const float* __restrict__ origin,
                            const float* __restrict__ focal,
                            const float* __restrict__ T12)
{
    if (blockIdx.x < TAB_BLOCKS) {
        int idx = blockIdx.x * blockDim.x + threadIdx.x;
        const int totalW = B_ * S_ * W_;
        const int totalH = B_ * S_ * H_;
        if (idx >= totalW + totalH) return;

        bool isW = idx < totalW;
        int rem  = isW ? idx : idx - totalW;
        int N    = isW ? W_ : H_;
        int pos  = rem % N;
        int s    = (rem / N) % S_;
        int b    = rem / (N * S_);

        float tz = T12[b * 3 + 2];
        float d  = (float)s;
        float D  = (s == 0) ? 0.0f : 1.0f / (1.0f / d + tz);
        float alpha = 1.0f - D * tz;

        float off;
        if (isW) off = D * tz * origin[b * 2 + 0] + D * focal[b * 2 + 0] * T12[b * 3 + 0];
        else     off = D * tz * origin[b * 2 + 1] + D * focal[b * 2 + 1] * T12[b * 3 + 1];

        float sp = alpha * (float)pos + off;
        float f0 = floorf(sp);
        float fr = sp - f0;
        int i0 = (int)f0;
        int i1 = i0 + 1;

        float w0 = (i0 >= 0 && i0 < N) ? (1.0f - fr) : 0.0f;
        float w1 = (i1 >= 0 && i1 < N) ? fr          : 0.0f;

        if (isW) {
            int ib; float wa, wb;
            if (i0 >= 0 && i0 < N)      { ib = i0; wa = w0; wb = w1; }
            else if (i0 == -1)          { ib = 0;  wa = w1; wb = 0.0f; }
            else                        { ib = min(max(i0, 0), N - 1); wa = 0.0f; wb = 0.0f; }
            int byteOff = (ib & 1) ? (COPYB + (ib + 1) * 64) : (ib * 64);
            int base = (b * S_ + s) * 2 * W_ + pos;
            WTab2 t0; t0.off = byteOff; t0.w = wa;
            WTab2 t1; t1.off = byteOff; t1.w = wb;
            d_wt2[base]      = t0;
            d_wt2[base + W_] = t1;
        } else {
            HTab t;
            int r0 = min(max(i0, 0), N - 1);
            int r1 = min(max(i1, 0), N - 1);
            t.r0 = (b * H_ + r0) * ROWB;
            t.r1 = (b * H_ + r1) * ROWB;
            t.h0 = w0;
            t.h1 = w1;
            d_ht[(b * S_ + s) * H_ + pos] = t;
        }
        return;
    }

    // --- conversion part ---
    int t = (blockIdx.x - TAB_BLOCKS) * blockDim.x + threadIdx.x;
    if (t >= CONV_THREADS) return;

    int c16  = t & 3;
    int rest = t >> 2;
    int wp   = rest % Wp_;  rest /= Wp_;
    int h    = rest % H_;
    int b    = rest / H_;

    uint4 o = make_uint4(0u, 0u, 0u, 0u);
    if (wp < W_) {
        const float4* src = x4 + ((((b * H_ + h) * W_ + wp) << 3) + (c16 << 1));
        float4 p = src[0];
        float4 q = src[1];
        __half2 a0 = __floats2half2_rn(p.x, p.y);
        __half2 a1 = __floats2half2_rn(p.z, p.w);
        __half2 a2 = __floats2half2_rn(q.x, q.y);
        __half2 a3 = __floats2half2_rn(q.z, q.w);
        o.x = *(unsigned int*)&a0;
        o.y = *(unsigned int*)&a1;
        o.z = *(unsigned int*)&a2;
        o.w = *(unsigned int*)&a3;
    }

    int rowChunk = (b * H_ + h) * Wp_ * 4;
    d_xs[rowChunk + wp * 4 + c16] = o;                                  // copy0[wp]
    if (wp + 1 < Wp_)
        d_xs[COPY_CHUNKS + rowChunk + (wp + 1) * 4 + c16] = o;          // copy1[wp+1] = x[wp]
    if (wp == 0)
        d_xs[COPY_CHUNKS + rowChunk + c16] = make_uint4(0u, 0u, 0u, 0u); // copy1[0] pad
    if (b == 0 && h == 0)
        d_xs[2 * COPY_CHUNKS + wp * 4 + c16] = make_uint4(0u, 0u, 0u, 0u); // final pad row
}

// ---------------------------------------------------------------------------
// Packed f32x2 helpers (sm_103a FFMA2)
// ---------------------------------------------------------------------------
__device__ __forceinline__ unsigned long long fma2_(unsigned long long a,
                                                    unsigned long long b,
                                                    unsigned long long c)
{
    unsigned long long d;
    asm("fma.rn.f32x2 %0, %1, %2, %3;" : "=l"(d) : "l"(a), "l"(b), "l"(c));
    return d;
}
__device__ __forceinline__ unsigned long long mul2_(unsigned long long a,
                                                    unsigned long long b)
{
    unsigned long long d;
    asm("mul.rn.f32x2 %0, %1, %2;" : "=l"(d) : "l"(a), "l"(b));
    return d;
}
__device__ __forceinline__ unsigned long long pack2_(float lo, float hi)
{
    unsigned long long d;
    asm("mov.b64 %0, {%1, %2};" : "=l"(d) : "f"(lo), "f"(hi));
    return d;
}
__device__ __forceinline__ __half2 u2h2_(unsigned int u)
{
    __half2 h; *(unsigned int*)&h = u; return h;
}

// ---------------------------------------------------------------------------
// Main kernel. Warp = 4 pixels x 8 chan-lanes. 8B record per
// (step, hl, wl, col):
//   { base = (m0!=0 ? r0 : r1-ROWB) + off,  half2(m0, m1) }
// Loads are weight-predicated (zero half-weight -> LDG skipped; predicate is
// per-pixel-uniform so the whole 128B line is saved). NO zero-init per step:
// tap registers live in arrays hoisted out of the loop, zeroed once. A
// skipped load leaves stale-but-FINITE data that is multiplied by an exact
// half 0 -> contributes exact 0. Bit-identical to R7 output.
// Inner loop: 1 LDS.64 + 2 ISETP + <=2 LDG.128 + half2 interp + f32x2 dot.
// ---------------------------------------------------------------------------
__global__ __launch_bounds__(256, 5) void corr_kernel(
    const float4* __restrict__ y4,
    float* __restrict__ out)
{
    const int tid  = threadIdx.x;
    const int wi   = tid >> 5;
    const int lane = tid & 31;
    const int sub  = lane >> 3;
    const int cg   = lane & 7;
    const int hiCol = (cg >> 2) & 1;

    int bx  = blockIdx.x;
    int twi = bx % (W_ / 8);
    int thi = (bx / (W_ / 8)) % (H_ / 4);
    int b   = bx / ((W_ / 8) * (H_ / 4));

    const int wl = (wi & 1) * 4 + sub;
    const int hl = wi >> 1;
    int w = twi * 8 + wl;
    int h = thi * 4 + hl;
    int p = (b * H_ + h) * W_ + w;

    // record table: idx = s*64 + hl*16 + wl*2 + col -> 2048 uint2 = 16 KB
    __shared__ uint2 srec[S_ * 4 * 8 * 2];

    // Build records: 8 per thread, coalesced STS.64.
#pragma unroll
    for (int k = 0; k < 8; ++k) {
        int r   = tid + k * 256;
        int col = r & 1;
        int wl2 = (r >> 1) & 7;
        int hl2 = (r >> 4) & 3;
        int s   = r >> 6;

        WTab2 wt = d_wt2[(b * S_ + s) * 2 * W_ + col * W_ + twi * 8 + wl2];
        HTab  ht = d_ht[(b * S_ + s) * H_ + thi * 4 + hl2];

        float m0 = ht.h0 * wt.w;
        float m1 = ht.h1 * wt.w;
        __half2 m01 = __floats2half2_rn(m0, m1);

        // If m0==0 (top border / OOB), anchor on r1 so base+ROWB = r1.
        int rbase = (m0 != 0.0f) ? ht.r0 : (ht.r1 - ROWB);

        uint2 rec;
        rec.x = (unsigned)(rbase + wt.off);
        rec.y = *(unsigned*)&m01;
        srec[r] = rec;
    }

    // y channels for this lane's group (fp32), pre-scaled by 1/C, packed f32x2
    unsigned long long z[4];
    {
        const float4* yp = y4 + (p << 3) + ((cg & 3) << 1);
        float4 a = yp[0], c = yp[1];
        const float sc = 1.0f / (float)C_;
        z[0] = pack2_(a.x * sc, a.y * sc);
        z[1] = pack2_(a.z * sc, a.w * sc);
        z[2] = pack2_(c.x * sc, c.y * sc);
        z[3] = pack2_(c.z * sc, c.w * sc);
    }

    __syncthreads();

    const char* xsbL = (const char*)d_xs + (cg << 4);
    const uint2* myrec = srec + (hl * 16 + wl * 2 + hiCol);
    float* outp = out + p * S_;

    // Tap registers: zeroed ONCE; skipped loads leave stale finite data that
    // is annihilated by its exact-zero half weight.
    uint4 Ar[4], Br[4];
#pragma unroll
    for (int i = 0; i < 4; ++i) {
        Ar[i] = make_uint4(0u, 0u, 0u, 0u);
        Br[i] = make_uint4(0u, 0u, 0u, 0u);
    }

#pragma unroll 1
    for (int g = 0; g < S_ / 4; ++g) {
        float pr[4];
#pragma unroll
        for (int i = 0; i < 4; ++i) {
            int s = g * 4 + i;
            uint2 rec = myrec[s * 64];
            unsigned m01u = rec.y;

            const char* pa = xsbL + (int)rec.x;
            if (m01u & 0x0000ffffu) Ar[i] = *(const uint4*)pa;
            if (m01u & 0xffff0000u) Br[i] = *(const uint4*)(pa + ROWB);

            __half2 m0h = u2h2_(__byte_perm(m01u, 0, 0x1010));
            __half2 m1h = u2h2_(__byte_perm(m01u, 0, 0x3232));

            __half2 v0 = __hfma2(m0h, u2h2_(Ar[i].x), __hmul2(m1h, u2h2_(Br[i].x)));
            __half2 v1 = __hfma2(m0h, u2h2_(Ar[i].y), __hmul2(m1h, u2h2_(Br[i].y)));
            __half2 v2 = __hfma2(m0h, u2h2_(Ar[i].z), __hmul2(m1h, u2h2_(Br[i].z)));
            __half2 v3 = __hfma2(m0h, u2h2_(Ar[i].w), __hmul2(m1h, u2h2_(Br[i].w)));

            float2 f0 = __half22float2(v0);
            float2 f1 = __half22float2(v1);
            float2 f2 = __half22float2(v2);
            float2 f3 = __half22float2(v3);

            unsigned long long acc = mul2_(pack2_(f0.x, f0.y), z[0]);
            acc = fma2_(pack2_(f1.x, f1.y), z[1], acc);
            acc = fma2_(pack2_(f2.x, f2.y), z[2], acc);
            acc = fma2_(pack2_(f3.x, f3.y), z[3], acc);

            float2 af = *(float2*)&acc;
            pr[i] = af.x + af.y;
        }

        // Butterfly: reduce 4 values over the 8 lanes of this pixel.
        float u = hiCol ? pr[0] : pr[2];
        float v = hiCol ? pr[1] : pr[3];
        u = __shfl_xor_sync(0xffffffffu, u, 4);
        v = __shfl_xor_sync(0xffffffffu, v, 4);
        float a  = hiCol ? (pr[2] + u) : (pr[0] + u);
        float bb = hiCol ? (pr[3] + v) : (pr[1] + v);
        bool hi2 = (cg & 2) != 0;
        float t = hi2 ? a : bb;
        t = __shfl_xor_sync(0xffffffffu, t, 2);
        float r = (hi2 ? bb : a) + t;
        r += __shfl_xor_sync(0xffffffffu, r, 1);

        if ((cg & 1) == 0) outp[g * 4 + (cg >> 1)] = r;
    }
}

// ---------------------------------------------------------------------------
extern "C" void kernel_launch(void* const* d_in, const int* in_sizes, int n_in,
                              void* d_out, int out_size)
{
    (void)in_sizes; (void)n_in; (void)out_size;
    const float* x      = (const float*)d_in[0];
    const float* y      = (const float*)d_in[1];
    const float* origin = (const float*)d_in[2];
    const float* focal  = (const float*)d_in[3];
    const float* T12    = (const float*)d_in[4];

    prep_kernel<<<TAB_BLOCKS + CONV_BLOCKS, 256>>>((const float4*)x, origin, focal, T12);

    int nBlocks = (W_ / 8) * (H_ / 4) * B_;   // 15360
    corr_kernel<<<nBlocks, 256>>>((const float4*)y, (float*)d_out);
}

// round 10
// speedup vs baseline: 2.0960x; 2.0960x over previous
#include <cuda_runtime.h>
#include <cuda_fp16.h>

// Problem constants
#define B_ 4
#define H_ 192
#define W_ 640
#define C_ 32
#define S_ 32

#define Wp_   (W_ + 2)                 // padded width
#define ROWB  (Wp_ * 64)               // bytes per row in fp16 scratch (64B/pixel)
#define COPYB (B_ * H_ * ROWB)         // bytes per parity copy

// Two parity-shifted fp16 copies of x: for base column ib, one aligned 128B
// region holds [ x[ib] | x[ib+1] ].
#define COPY_CHUNKS (B_ * H_ * Wp_ * 4)
#define XS_CHUNKS   (2 * COPY_CHUNKS + Wp_ * 4)
__device__ uint4 d_xs[XS_CHUNKS];

// w-table: per (b,s,col,w): { byte-offset (incl. parity-copy base), weight fp32 }
struct __align__(8) WTab2 { int off; float w; };
__device__ WTab2 d_wt2[B_ * S_ * 2 * W_];
// h-table: per (b,s,h): { row0 byte base, row1 byte base, h0 fp32, h1 fp32 }
struct __align__(16) HTab { int r0, r1; float h0, h1; };
__device__ HTab d_ht[B_ * S_ * H_];

#define TAB_THREADS (B_ * S_ * (W_ + H_))
#define TAB_BLOCKS  ((TAB_THREADS + 255) / 256)
#define CONV_THREADS (B_ * H_ * Wp_ * 4)
#define CONV_BLOCKS  ((CONV_THREADS + 255) / 256)

// ---------------------------------------------------------------------------
// Fused prep kernel: table build + fp16 conversion (x read once).
// ---------------------------------------------------------------------------
__global__ void prep_kernel(const float4* __restrict__ x4,
                            const float* __restrict__ origin,
                            const float* __restrict__ focal,
                            const float* __restrict__ T12)
{
    if (blockIdx.x < TAB_BLOCKS) {
        int idx = blockIdx.x * blockDim.x + threadIdx.x;
        const int totalW = B_ * S_ * W_;
        const int totalH = B_ * S_ * H_;
        if (idx >= totalW + totalH) return;

        bool isW = idx < totalW;
        int rem  = isW ? idx : idx - totalW;
        int N    = isW ? W_ : H_;
        int pos  = rem % N;
        int s    = (rem / N) % S_;
        int b    = rem / (N * S_);

        float tz = T12[b * 3 + 2];
        float d  = (float)s;
        float D  = (s == 0) ? 0.0f : 1.0f / (1.0f / d + tz);
        float alpha = 1.0f - D * tz;

        float off;
        if (isW) off = D * tz * origin[b * 2 + 0] + D * focal[b * 2 + 0] * T12[b * 3 + 0];
        else     off = D * tz * origin[b * 2 + 1] + D * focal[b * 2 + 1] * T12[b * 3 + 1];

        float sp = alpha * (float)pos + off;
        float f0 = floorf(sp);
        float fr = sp - f0;
        int i0 = (int)f0;
        int i1 = i0 + 1;

        float w0 = (i0 >= 0 && i0 < N) ? (1.0f - fr) : 0.0f;
        float w1 = (i1 >= 0 && i1 < N) ? fr          : 0.0f;

        if (isW) {
            int ib; float wa, wb;
            if (i0 >= 0 && i0 < N)      { ib = i0; wa = w0; wb = w1; }
            else if (i0 == -1)          { ib = 0;  wa = w1; wb = 0.0f; }
            else                        { ib = min(max(i0, 0), N - 1); wa = 0.0f; wb = 0.0f; }
            int byteOff = (ib & 1) ? (COPYB + (ib + 1) * 64) : (ib * 64);
            int base = (b * S_ + s) * 2 * W_ + pos;
            WTab2 t0; t0.off = byteOff; t0.w = wa;
            WTab2 t1; t1.off = byteOff; t1.w = wb;
            d_wt2[base]      = t0;
            d_wt2[base + W_] = t1;
        } else {
            HTab t;
            int r0 = min(max(i0, 0), N - 1);
            int r1 = min(max(i1, 0), N - 1);
            t.r0 = (b * H_ + r0) * ROWB;
            t.r1 = (b * H_ + r1) * ROWB;
            t.h0 = w0;
            t.h1 = w1;
            d_ht[(b * S_ + s) * H_ + pos] = t;
        }
        return;
    }

    // --- conversion part ---
    int t = (blockIdx.x - TAB_BLOCKS) * blockDim.x + threadIdx.x;
    if (t >= CONV_THREADS) return;

    int c16  = t & 3;
    int rest = t >> 2;
    int wp   = rest % Wp_;  rest /= Wp_;
    int h    = rest % H_;
    int b    = rest / H_;

    uint4 o = make_uint4(0u, 0u, 0u, 0u);
    if (wp < W_) {
        const float4* src = x4 + ((((b * H_ + h) * W_ + wp) << 3) + (c16 << 1));
        float4 p = src[0];
        float4 q = src[1];
        __half2 a0 = __floats2half2_rn(p.x, p.y);
        __half2 a1 = __floats2half2_rn(p.z, p.w);
        __half2 a2 = __floats2half2_rn(q.x, q.y);
        __half2 a3 = __floats2half2_rn(q.z, q.w);
        o.x = *(unsigned int*)&a0;
        o.y = *(unsigned int*)&a1;
        o.z = *(unsigned int*)&a2;
        o.w = *(unsigned int*)&a3;
    }

    int rowChunk = (b * H_ + h) * Wp_ * 4;
    d_xs[rowChunk + wp * 4 + c16] = o;                                  // copy0[wp]
    if (wp + 1 < Wp_)
        d_xs[COPY_CHUNKS + rowChunk + (wp + 1) * 4 + c16] = o;          // copy1[wp+1] = x[wp]
    if (wp == 0)
        d_xs[COPY_CHUNKS + rowChunk + c16] = make_uint4(0u, 0u, 0u, 0u); // copy1[0] pad
    if (b == 0 && h == 0)
        d_xs[2 * COPY_CHUNKS + wp * 4 + c16] = make_uint4(0u, 0u, 0u, 0u); // final pad row
}

__device__ __forceinline__ __half2 u2h2_(unsigned int u)
{
    __half2 h; *(unsigned int*)&h = u; return h;
}

// ---------------------------------------------------------------------------
// Main kernel. Warp = 4 pixels x 8 chan-lanes. 8B record per
// (step, hl, wl, col):
//   { base = (m0!=0 ? r0 : r1-ROWB) + off,  half2(m0, m1) }
// Loads are weight-predicated (zero half-weight -> LDG skipped; predicate is
// per-pixel-uniform so the whole 128B line is saved). Tap registers are
// per-iteration scalars with zero-init (transient -> no spill; R9 lesson).
// Dot product is now FULLY fp16 (y pre-converted to half2, scaled by 1/C):
//   d = v0*y0 + v1*y1 + v2*y2 + v3*y3  (1 HMUL2 + 3 HFMA2)
// then one half2->float2 convert + fp32 butterfly reduce.
// ---------------------------------------------------------------------------
__global__ __launch_bounds__(256, 5) void corr_kernel(
    const float4* __restrict__ y4,
    float* __restrict__ out)
{
    const int tid  = threadIdx.x;
    const int wi   = tid >> 5;
    const int lane = tid & 31;
    const int sub  = lane >> 3;
    const int cg   = lane & 7;
    const int hiCol = (cg >> 2) & 1;

    int bx  = blockIdx.x;
    int twi = bx % (W_ / 8);
    int thi = (bx / (W_ / 8)) % (H_ / 4);
    int b   = bx / ((W_ / 8) * (H_ / 4));

    const int wl = (wi & 1) * 4 + sub;
    const int hl = wi >> 1;
    int w = twi * 8 + wl;
    int h = thi * 4 + hl;
    int p = (b * H_ + h) * W_ + w;

    // record table: idx = s*64 + hl*16 + wl*2 + col -> 2048 uint2 = 16 KB
    __shared__ uint2 srec[S_ * 4 * 8 * 2];

    // Build records: 8 per thread, coalesced STS.64.
#pragma unroll
    for (int k = 0; k < 8; ++k) {
        int r   = tid + k * 256;
        int col = r & 1;
        int wl2 = (r >> 1) & 7;
        int hl2 = (r >> 4) & 3;
        int s   = r >> 6;

        WTab2 wt = d_wt2[(b * S_ + s) * 2 * W_ + col * W_ + twi * 8 + wl2];
        HTab  ht = d_ht[(b * S_ + s) * H_ + thi * 4 + hl2];

        float m0 = ht.h0 * wt.w;
        float m1 = ht.h1 * wt.w;
        __half2 m01 = __floats2half2_rn(m0, m1);

        // If m0==0 (top border / OOB), anchor on r1 so base+ROWB = r1.
        int rbase = (m0 != 0.0f) ? ht.r0 : (ht.r1 - ROWB);

        uint2 rec;
        rec.x = (unsigned)(rbase + wt.off);
        rec.y = *(unsigned*)&m01;
        srec[r] = rec;
    }

    // y channels for this lane's group, pre-scaled by 1/C, converted to half2
    __half2 yh[4];
    {
        const float4* yp = y4 + (p << 3) + ((cg & 3) << 1);
        float4 a = yp[0], c = yp[1];
        const float sc = 1.0f / (float)C_;
        yh[0] = __floats2half2_rn(a.x * sc, a.y * sc);
        yh[1] = __floats2half2_rn(a.z * sc, a.w * sc);
        yh[2] = __floats2half2_rn(c.x * sc, c.y * sc);
        yh[3] = __floats2half2_rn(c.z * sc, c.w * sc);
    }

    __syncthreads();

    const char* xsbL = (const char*)d_xs + (cg << 4);
    const uint2* myrec = srec + (hl * 16 + wl * 2 + hiCol);
    float* outp = out + p * S_;

#pragma unroll 1
    for (int g = 0; g < S_ / 4; ++g) {
        float pr[4];
#pragma unroll
        for (int i = 0; i < 4; ++i) {
            int s = g * 4 + i;
            uint2 rec = myrec[s * 64];
            unsigned m01u = rec.y;

            uint4 A  = make_uint4(0u, 0u, 0u, 0u);
            uint4 Bv = make_uint4(0u, 0u, 0u, 0u);
            const char* pa = xsbL + (int)rec.x;
            if (m01u & 0x0000ffffu) A  = *(const uint4*)pa;
            if (m01u & 0xffff0000u) Bv = *(const uint4*)(pa + ROWB);

            __half2 m0h = u2h2_(__byte_perm(m01u, 0, 0x1010));
            __half2 m1h = u2h2_(__byte_perm(m01u, 0, 0x3232));

            __half2 v0 = __hfma2(m0h, u2h2_(A.x), __hmul2(m1h, u2h2_(Bv.x)));
            __half2 v1 = __hfma2(m0h, u2h2_(A.y), __hmul2(m1h, u2h2_(Bv.y)));
            __half2 v2 = __hfma2(m0h, u2h2_(A.z), __hmul2(m1h, u2h2_(Bv.z)));
            __half2 v3 = __hfma2(m0h, u2h2_(A.w), __hmul2(m1h, u2h2_(Bv.w)));

            // fp16 channel dot (packed), single convert at the end
            __half2 dh = __hmul2(v0, yh[0]);
            dh = __hfma2(v1, yh[1], dh);
            dh = __hfma2(v2, yh[2], dh);
            dh = __hfma2(v3, yh[3], dh);

            float2 df = __half22float2(dh);
            pr[i] = df.x + df.y;
        }

        // Butterfly: reduce 4 values over the 8 lanes of this pixel (fp32).
        float u = hiCol ? pr[0] : pr[2];
        float v = hiCol ? pr[1] : pr[3];
        u = __shfl_xor_sync(0xffffffffu, u, 4);
        v = __shfl_xor_sync(0xffffffffu, v, 4);
        float a  = hiCol ? (pr[2] + u) : (pr[0] + u);
        float bb = hiCol ? (pr[3] + v) : (pr[1] + v);
        bool hi2 = (cg & 2) != 0;
        float t = hi2 ? a : bb;
        t = __shfl_xor_sync(0xffffffffu, t, 2);
        float r = (hi2 ? bb : a) + t;
        r += __shfl_xor_sync(0xffffffffu, r, 1);

        if ((cg & 1) == 0) outp[g * 4 + (cg >> 1)] = r;
    }
}

// ---------------------------------------------------------------------------
extern "C" void kernel_launch(void* const* d_in, const int* in_sizes, int n_in,
                              void* d_out, int out_size)
{
    (void)in_sizes; (void)n_in; (void)out_size;
    const float* x      = (const float*)d_in[0];
    const float* y      = (const float*)d_in[1];
    const float* origin = (const float*)d_in[2];
    const float* focal  = (const float*)d_in[3];
    const float* T12    = (const float*)d_in[4];

    prep_kernel<<<TAB_BLOCKS + CONV_BLOCKS, 256>>>((const float4*)x, origin, focal, T12);

    int nBlocks = (W_ / 8) * (H_ / 4) * B_;   // 15360
    corr_kernel<<<nBlocks, 256>>>((const float4*)y, (float*)d_out);
}

// round 11
// speedup vs baseline: 2.3272x; 1.1103x over previous
#include <cuda_runtime.h>
#include <cuda_fp16.h>

// Problem constants
#define B_ 4
#define H_ 192
#define W_ 640
#define C_ 32
#define S_ 32

#define Wp_   (W_ + 2)                 // padded width
#define ROWB  (Wp_ * 64)               // bytes per row in fp16 scratch (64B/pixel)
#define COPYB (B_ * H_ * ROWB)         // bytes per parity copy

// Two parity-shifted fp16 copies of x: for base column ib, one aligned 128B
// region holds [ x[ib] | x[ib+1] ].
#define COPY_CHUNKS (B_ * H_ * Wp_ * 4)
#define XS_CHUNKS   (2 * COPY_CHUNKS + Wp_ * 4)
__device__ uint4 d_xs[XS_CHUNKS];

// w-table: per (b,s,col,w): { byte-offset (incl. parity-copy base), weight fp32 }
struct __align__(8) WTab2 { int off; float w; };
__device__ WTab2 d_wt2[B_ * S_ * 2 * W_];
// h-table: per (b,s,h): { row0 byte base, row1 byte base, h0 fp32, h1 fp32 }
struct __align__(16) HTab { int r0, r1; float h0, h1; };
__device__ HTab d_ht[B_ * S_ * H_];

#define TAB_THREADS (B_ * S_ * (W_ + H_))
#define TAB_BLOCKS  ((TAB_THREADS + 255) / 256)
#define CONV_THREADS (B_ * H_ * Wp_ * 4)
#define CONV_BLOCKS  ((CONV_THREADS + 255) / 256)

// ---------------------------------------------------------------------------
// Fused prep kernel: table build + fp16 conversion (x read once).
// ---------------------------------------------------------------------------
__global__ void prep_kernel(const float4* __restrict__ x4,
                            const float* __restrict__ origin,
                            const float* __restrict__ focal,
                            const float* __restrict__ T12)
{
    if (blockIdx.x < TAB_BLOCKS) {
        int idx = blockIdx.x * blockDim.x + threadIdx.x;
        const int totalW = B_ * S_ * W_;
        const int totalH = B_ * S_ * H_;
        if (idx >= totalW + totalH) return;

        bool isW = idx < totalW;
        int rem  = isW ? idx : idx - totalW;
        int N    = isW ? W_ : H_;
        int pos  = rem % N;
        int s    = (rem / N) % S_;
        int b    = rem / (N * S_);

        float tz = T12[b * 3 + 2];
        float d  = (float)s;
        float D  = (s == 0) ? 0.0f : 1.0f / (1.0f / d + tz);
        float alpha = 1.0f - D * tz;

        float off;
        if (isW) off = D * tz * origin[b * 2 + 0] + D * focal[b * 2 + 0] * T12[b * 3 + 0];
        else     off = D * tz * origin[b * 2 + 1] + D * focal[b * 2 + 1] * T12[b * 3 + 1];

        float sp = alpha * (float)pos + off;
        float f0 = floorf(sp);
        float fr = sp - f0;
        int i0 = (int)f0;
        int i1 = i0 + 1;

        float w0 = (i0 >= 0 && i0 < N) ? (1.0f - fr) : 0.0f;
        float w1 = (i1 >= 0 && i1 < N) ? fr          : 0.0f;

        if (isW) {
            int ib; float wa, wb;
            if (i0 >= 0 && i0 < N)      { ib = i0; wa = w0; wb = w1; }
            else if (i0 == -1)          { ib = 0;  wa = w1; wb = 0.0f; }
            else                        { ib = min(max(i0, 0), N - 1); wa = 0.0f; wb = 0.0f; }
            int byteOff = (ib & 1) ? (COPYB + (ib + 1) * 64) : (ib * 64);
            int base = (b * S_ + s) * 2 * W_ + pos;
            WTab2 t0; t0.off = byteOff; t0.w = wa;
            WTab2 t1; t1.off = byteOff; t1.w = wb;
            d_wt2[base]      = t0;
            d_wt2[base + W_] = t1;
        } else {
            HTab t;
            int r0 = min(max(i0, 0), N - 1);
            int r1 = min(max(i1, 0), N - 1);
            t.r0 = (b * H_ + r0) * ROWB;
            t.r1 = (b * H_ + r1) * ROWB;
            t.h0 = w0;
            t.h1 = w1;
            d_ht[(b * S_ + s) * H_ + pos] = t;
        }
        return;
    }

    // --- conversion part ---
    int t = (blockIdx.x - TAB_BLOCKS) * blockDim.x + threadIdx.x;
    if (t >= CONV_THREADS) return;

    int c16  = t & 3;
    int rest = t >> 2;
    int wp   = rest % Wp_;  rest /= Wp_;
    int h    = rest % H_;
    int b    = rest / H_;

    uint4 o = make_uint4(0u, 0u, 0u, 0u);
    if (wp < W_) {
        const float4* src = x4 + ((((b * H_ + h) * W_ + wp) << 3) + (c16 << 1));
        float4 p = src[0];
        float4 q = src[1];
        __half2 a0 = __floats2half2_rn(p.x, p.y);
        __half2 a1 = __floats2half2_rn(p.z, p.w);
        __half2 a2 = __floats2half2_rn(q.x, q.y);
        __half2 a3 = __floats2half2_rn(q.z, q.w);
        o.x = *(unsigned int*)&a0;
        o.y = *(unsigned int*)&a1;
        o.z = *(unsigned int*)&a2;
        o.w = *(unsigned int*)&a3;
    }

    int rowChunk = (b * H_ + h) * Wp_ * 4;
    d_xs[rowChunk + wp * 4 + c16] = o;                                  // copy0[wp]
    if (wp + 1 < Wp_)
        d_xs[COPY_CHUNKS + rowChunk + (wp + 1) * 4 + c16] = o;          // copy1[wp+1] = x[wp]
    if (wp == 0)
        d_xs[COPY_CHUNKS + rowChunk + c16] = make_uint4(0u, 0u, 0u, 0u); // copy1[0] pad
    if (b == 0 && h == 0)
        d_xs[2 * COPY_CHUNKS + wp * 4 + c16] = make_uint4(0u, 0u, 0u, 0u); // final pad row
}

__device__ __forceinline__ __half2 u2h2_(unsigned int u)
{
    __half2 h; *(unsigned int*)&h = u; return h;
}

// ---------------------------------------------------------------------------
// Main kernel. Warp = 4 pixels x 8 chan-lanes. 8B record per
// (step, hl, wl, col):
//   { base = (m0!=0 ? r0 : r1-ROWB) + off,  half2(m0, m1) }
// Per step:
//   - WARP-UNIFORM SKIP: a warp covers one image row; when the whole warp's
//     weights are zero (row/tile fully OOB -- frequent at high s), branch
//     around all loads+math (pr=0, exactly what the math would produce).
//   - Otherwise: weight-predicated LDGs (zero half-weight -> line skipped),
//     per-step zero-init (transient regs, no spill), fp16 dot restructured as
//     d = m0*(A.y) + m1*(B.y): 10 half2 ops (was 12), A/B die earlier.
// ---------------------------------------------------------------------------
__global__ __launch_bounds__(256, 5) void corr_kernel(
    const float4* __restrict__ y4,
    float* __restrict__ out)
{
    const int tid  = threadIdx.x;
    const int wi   = tid >> 5;
    const int lane = tid & 31;
    const int sub  = lane >> 3;
    const int cg   = lane & 7;
    const int hiCol = (cg >> 2) & 1;

    int bx  = blockIdx.x;
    int twi = bx % (W_ / 8);
    int thi = (bx / (W_ / 8)) % (H_ / 4);
    int b   = bx / ((W_ / 8) * (H_ / 4));

    const int wl = (wi & 1) * 4 + sub;
    const int hl = wi >> 1;
    int w = twi * 8 + wl;
    int h = thi * 4 + hl;
    int p = (b * H_ + h) * W_ + w;

    // record table: idx = s*64 + hl*16 + wl*2 + col -> 2048 uint2 = 16 KB
    __shared__ uint2 srec[S_ * 4 * 8 * 2];

    // Build records: 8 per thread, coalesced STS.64.
#pragma unroll
    for (int k = 0; k < 8; ++k) {
        int r   = tid + k * 256;
        int col = r & 1;
        int wl2 = (r >> 1) & 7;
        int hl2 = (r >> 4) & 3;
        int s   = r >> 6;

        WTab2 wt = d_wt2[(b * S_ + s) * 2 * W_ + col * W_ + twi * 8 + wl2];
        HTab  ht = d_ht[(b * S_ + s) * H_ + thi * 4 + hl2];

        float m0 = ht.h0 * wt.w;
        float m1 = ht.h1 * wt.w;
        __half2 m01 = __floats2half2_rn(m0, m1);

        // If m0==0 (top border / OOB), anchor on r1 so base+ROWB = r1.
        int rbase = (m0 != 0.0f) ? ht.r0 : (ht.r1 - ROWB);

        uint2 rec;
        rec.x = (unsigned)(rbase + wt.off);
        rec.y = *(unsigned*)&m01;
        srec[r] = rec;
    }

    // y channels for this lane's group, pre-scaled by 1/C, converted to half2
    __half2 yh[4];
    {
        const float4* yp = y4 + (p << 3) + ((cg & 3) << 1);
        float4 a = yp[0], c = yp[1];
        const float sc = 1.0f / (float)C_;
        yh[0] = __floats2half2_rn(a.x * sc, a.y * sc);
        yh[1] = __floats2half2_rn(a.z * sc, a.w * sc);
        yh[2] = __floats2half2_rn(c.x * sc, c.y * sc);
        yh[3] = __floats2half2_rn(c.z * sc, c.w * sc);
    }

    __syncthreads();

    const char* xsbL = (const char*)d_xs + (cg << 4);
    const uint2* myrec = srec + (hl * 16 + wl * 2 + hiCol);
    float* outp = out + p * S_;

#pragma unroll 1
    for (int g = 0; g < S_ / 4; ++g) {
        float pr[4];
#pragma unroll
        for (int i = 0; i < 4; ++i) {
            int s = g * 4 + i;
            uint2 rec = myrec[s * 64];
            unsigned m01u = rec.y;

            // Warp-uniform skip: whole row/tile out of bounds for this step.
            if (__any_sync(0xffffffffu, m01u != 0u)) {
                uint4 A  = make_uint4(0u, 0u, 0u, 0u);
                uint4 Bv = make_uint4(0u, 0u, 0u, 0u);
                const char* pa = xsbL + (int)rec.x;
                if (m01u & 0x0000ffffu) A  = *(const uint4*)pa;
                if (m01u & 0xffff0000u) Bv = *(const uint4*)(pa + ROWB);

                // dotA = A.y, dotB = B.y (packed fp16)
                __half2 dA = __hmul2(u2h2_(A.x), yh[0]);
                dA = __hfma2(u2h2_(A.y), yh[1], dA);
                dA = __hfma2(u2h2_(A.z), yh[2], dA);
                dA = __hfma2(u2h2_(A.w), yh[3], dA);

                __half2 dB = __hmul2(u2h2_(Bv.x), yh[0]);
                dB = __hfma2(u2h2_(Bv.y), yh[1], dB);
                dB = __hfma2(u2h2_(Bv.z), yh[2], dB);
                dB = __hfma2(u2h2_(Bv.w), yh[3], dB);

                __half2 m0h = u2h2_(__byte_perm(m01u, 0, 0x1010));
                __half2 m1h = u2h2_(__byte_perm(m01u, 0, 0x3232));
                __half2 dh  = __hfma2(m1h, dB, __hmul2(m0h, dA));

                float2 df = __half22float2(dh);
                pr[i] = df.x + df.y;
            } else {
                pr[i] = 0.0f;
            }
        }

        // Butterfly: reduce 4 values over the 8 lanes of this pixel (fp32).
        float u = hiCol ? pr[0] : pr[2];
        float v = hiCol ? pr[1] : pr[3];
        u = __shfl_xor_sync(0xffffffffu, u, 4);
        v = __shfl_xor_sync(0xffffffffu, v, 4);
        float a  = hiCol ? (pr[2] + u) : (pr[0] + u);
        float bb = hiCol ? (pr[3] + v) : (pr[1] + v);
        bool hi2 = (cg & 2) != 0;
        float t = hi2 ? a : bb;
        t = __shfl_xor_sync(0xffffffffu, t, 2);
        float r = (hi2 ? bb : a) + t;
        r += __shfl_xor_sync(0xffffffffu, r, 1);

        if ((cg & 1) == 0) outp[g * 4 + (cg >> 1)] = r;
    }
}

// ---------------------------------------------------------------------------
extern "C" void kernel_launch(void* const* d_in, const int* in_sizes, int n_in,
                              void* d_out, int out_size)
{
    (void)in_sizes; (void)n_in; (void)out_size;
    const float* x      = (const float*)d_in[0];
    const float* y      = (const float*)d_in[1];
    const float* origin = (const float*)d_in[2];
    const float* focal  = (const float*)d_in[3];
    const float* T12    = (const float*)d_in[4];

    prep_kernel<<<TAB_BLOCKS + CONV_BLOCKS, 256>>>((const float4*)x, origin, focal, T12);

    int nBlocks = (W_ / 8) * (H_ / 4) * B_;   // 15360
    corr_kernel<<<nBlocks, 256>>>((const float4*)y, (float*)d_out);
}

// round 12
// speedup vs baseline: 2.4707x; 1.0617x over previous
#include <cuda_runtime.h>
#include <cuda_fp16.h>

// Problem constants
#define B_ 4
#define H_ 192
#define W_ 640
#define C_ 32
#define S_ 32

#define Wp_   (W_ + 2)                 // padded width
#define ROWB  (Wp_ * 64)               // bytes per row in fp16 scratch (64B/pixel)
#define COPYB (B_ * H_ * ROWB)         // bytes per parity copy

// Two parity-shifted fp16 copies of x: for base column ib, one aligned 128B
// region holds [ x[ib] | x[ib+1] ].
#define COPY_CHUNKS (B_ * H_ * Wp_ * 4)
#define XS_CHUNKS   (2 * COPY_CHUNKS + Wp_ * 4)
__device__ uint4 d_xs[XS_CHUNKS];

// w-table: per (b,s,col,w): { byte-offset (incl. parity-copy base), weight fp32 }
struct __align__(8) WTab2 { int off; float w; };
__device__ WTab2 d_wt2[B_ * S_ * 2 * W_];
// h-table: per (b,s,h): { row0 byte base, row1 byte base, h0 fp32, h1 fp32 }
struct __align__(16) HTab { int r0, r1; float h0, h1; };
__device__ HTab d_ht[B_ * S_ * H_];

#define TAB_THREADS (B_ * S_ * (W_ + H_))
#define TAB_BLOCKS  ((TAB_THREADS + 255) / 256)
#define CONV_THREADS (B_ * H_ * Wp_ * 4)
#define CONV_BLOCKS  ((CONV_THREADS + 255) / 256)

// ---------------------------------------------------------------------------
// Fused prep kernel: table build + fp16 conversion (x read once).
// ---------------------------------------------------------------------------
__global__ void prep_kernel(const float4* __restrict__ x4,
                            const float* __restrict__ origin,
                            const float* __restrict__ focal,
                            const float* __restrict__ T12)
{
    if (blockIdx.x < TAB_BLOCKS) {
        int idx = blockIdx.x * blockDim.x + threadIdx.x;
        const int totalW = B_ * S_ * W_;
        const int totalH = B_ * S_ * H_;
        if (idx >= totalW + totalH) return;

        bool isW = idx < totalW;
        int rem  = isW ? idx : idx - totalW;
        int N    = isW ? W_ : H_;
        int pos  = rem % N;
        int s    = (rem / N) % S_;
        int b    = rem / (N * S_);

        float tz = T12[b * 3 + 2];
        float d  = (float)s;
        float D  = (s == 0) ? 0.0f : 1.0f / (1.0f / d + tz);
        float alpha = 1.0f - D * tz;

        float off;
        if (isW) off = D * tz * origin[b * 2 + 0] + D * focal[b * 2 + 0] * T12[b * 3 + 0];
        else     off = D * tz * origin[b * 2 + 1] + D * focal[b * 2 + 1] * T12[b * 3 + 1];

        float sp = alpha * (float)pos + off;
        float f0 = floorf(sp);
        float fr = sp - f0;
        int i0 = (int)f0;
        int i1 = i0 + 1;

        float w0 = (i0 >= 0 && i0 < N) ? (1.0f - fr) : 0.0f;
        float w1 = (i1 >= 0 && i1 < N) ? fr          : 0.0f;

        if (isW) {
            int ib; float wa, wb;
            if (i0 >= 0 && i0 < N)      { ib = i0; wa = w0; wb = w1; }
            else if (i0 == -1)          { ib = 0;  wa = w1; wb = 0.0f; }
            else                        { ib = min(max(i0, 0), N - 1); wa = 0.0f; wb = 0.0f; }
            int byteOff = (ib & 1) ? (COPYB + (ib + 1) * 64) : (ib * 64);
            int base = (b * S_ + s) * 2 * W_ + pos;
            WTab2 t0; t0.off = byteOff; t0.w = wa;
            WTab2 t1; t1.off = byteOff; t1.w = wb;
            d_wt2[base]      = t0;
            d_wt2[base + W_] = t1;
        } else {
            HTab t;
            int r0 = min(max(i0, 0), N - 1);
            int r1 = min(max(i1, 0), N - 1);
            t.r0 = (b * H_ + r0) * ROWB;
            t.r1 = (b * H_ + r1) * ROWB;
            t.h0 = w0;
            t.h1 = w1;
            d_ht[(b * S_ + s) * H_ + pos] = t;
        }
        return;
    }

    // --- conversion part ---
    int t = (blockIdx.x - TAB_BLOCKS) * blockDim.x + threadIdx.x;
    if (t >= CONV_THREADS) return;

    int c16  = t & 3;
    int rest = t >> 2;
    int wp   = rest % Wp_;  rest /= Wp_;
    int h    = rest % H_;
    int b    = rest / H_;

    uint4 o = make_uint4(0u, 0u, 0u, 0u);
    if (wp < W_) {
        const float4* src = x4 + ((((b * H_ + h) * W_ + wp) << 3) + (c16 << 1));
        float4 p = src[0];
        float4 q = src[1];
        __half2 a0 = __floats2half2_rn(p.x, p.y);
        __half2 a1 = __floats2half2_rn(p.z, p.w);
        __half2 a2 = __floats2half2_rn(q.x, q.y);
        __half2 a3 = __floats2half2_rn(q.z, q.w);
        o.x = *(unsigned int*)&a0;
        o.y = *(unsigned int*)&a1;
        o.z = *(unsigned int*)&a2;
        o.w = *(unsigned int*)&a3;
    }

    int rowChunk = (b * H_ + h) * Wp_ * 4;
    d_xs[rowChunk + wp * 4 + c16] = o;                                  // copy0[wp]
    if (wp + 1 < Wp_)
        d_xs[COPY_CHUNKS + rowChunk + (wp + 1) * 4 + c16] = o;          // copy1[wp+1] = x[wp]
    if (wp == 0)
        d_xs[COPY_CHUNKS + rowChunk + c16] = make_uint4(0u, 0u, 0u, 0u); // copy1[0] pad
    if (b == 0 && h == 0)
        d_xs[2 * COPY_CHUNKS + wp * 4 + c16] = make_uint4(0u, 0u, 0u, 0u); // final pad row
}

__device__ __forceinline__ __half2 u2h2_(unsigned int u)
{
    __half2 h; *(unsigned int*)&h = u; return h;
}

// ---------------------------------------------------------------------------
// Main kernel. Identical structure to R11 (warp-uniform skip + predicated
// LDGs + fp16 dot), with occupancy pushed 5 -> 6 blocks/SM (reg cap 42) to
// close the ~38us exposed-latency gap seen at occ=5 (issue 60%, L1 76%,
// neither saturated). Live register state is small post-fp16-dot; 42 should
// fit without spills (watch L2% for the spill signature).
// ---------------------------------------------------------------------------
__global__ __launch_bounds__(256, 6) void corr_kernel(
    const float4* __restrict__ y4,
    float* __restrict__ out)
{
    const int tid  = threadIdx.x;
    const int wi   = tid >> 5;
    const int lane = tid & 31;
    const int sub  = lane >> 3;
    const int cg   = lane & 7;
    const int hiCol = (cg >> 2) & 1;

    int bx  = blockIdx.x;
    int twi = bx % (W_ / 8);
    int thi = (bx / (W_ / 8)) % (H_ / 4);
    int b   = bx / ((W_ / 8) * (H_ / 4));

    const int wl = (wi & 1) * 4 + sub;
    const int hl = wi >> 1;
    int w = twi * 8 + wl;
    int h = thi * 4 + hl;
    int p = (b * H_ + h) * W_ + w;

    // record table: idx = s*64 + hl*16 + wl*2 + col -> 2048 uint2 = 16 KB
    __shared__ uint2 srec[S_ * 4 * 8 * 2];

    // Build records: 8 per thread, coalesced STS.64.
#pragma unroll
    for (int k = 0; k < 8; ++k) {
        int r   = tid + k * 256;
        int col = r & 1;
        int wl2 = (r >> 1) & 7;
        int hl2 = (r >> 4) & 3;
        int s   = r >> 6;

        WTab2 wt = d_wt2[(b * S_ + s) * 2 * W_ + col * W_ + twi * 8 + wl2];
        HTab  ht = d_ht[(b * S_ + s) * H_ + thi * 4 + hl2];

        float m0 = ht.h0 * wt.w;
        float m1 = ht.h1 * wt.w;
        __half2 m01 = __floats2half2_rn(m0, m1);

        // If m0==0 (top border / OOB), anchor on r1 so base+ROWB = r1.
        int rbase = (m0 != 0.0f) ? ht.r0 : (ht.r1 - ROWB);

        uint2 rec;
        rec.x = (unsigned)(rbase + wt.off);
        rec.y = *(unsigned*)&m01;
        srec[r] = rec;
    }

    // y channels for this lane's group, pre-scaled by 1/C, converted to half2
    __half2 yh[4];
    {
        const float4* yp = y4 + (p << 3) + ((cg & 3) << 1);
        float4 a = yp[0], c = yp[1];
        const float sc = 1.0f / (float)C_;
        yh[0] = __floats2half2_rn(a.x * sc, a.y * sc);
        yh[1] = __floats2half2_rn(a.z * sc, a.w * sc);
        yh[2] = __floats2half2_rn(c.x * sc, c.y * sc);
        yh[3] = __floats2half2_rn(c.z * sc, c.w * sc);
    }

    __syncthreads();

    const char* xsbL = (const char*)d_xs + (cg << 4);
    const uint2* myrec = srec + (hl * 16 + wl * 2 + hiCol);
    float* outp = out + p * S_;

#pragma unroll 1
    for (int g = 0; g < S_ / 4; ++g) {
        float pr[4];
#pragma unroll
        for (int i = 0; i < 4; ++i) {
            int s = g * 4 + i;
            uint2 rec = myrec[s * 64];
            unsigned m01u = rec.y;

            // Warp-uniform skip: whole row/tile out of bounds for this step.
            if (__any_sync(0xffffffffu, m01u != 0u)) {
                uint4 A  = make_uint4(0u, 0u, 0u, 0u);
                uint4 Bv = make_uint4(0u, 0u, 0u, 0u);
                const char* pa = xsbL + (int)rec.x;
                if (m01u & 0x0000ffffu) A  = *(const uint4*)pa;
                if (m01u & 0xffff0000u) Bv = *(const uint4*)(pa + ROWB);

                // dotA = A.y, dotB = B.y (packed fp16)
                __half2 dA = __hmul2(u2h2_(A.x), yh[0]);
                dA = __hfma2(u2h2_(A.y), yh[1], dA);
                dA = __hfma2(u2h2_(A.z), yh[2], dA);
                dA = __hfma2(u2h2_(A.w), yh[3], dA);

                __half2 dB = __hmul2(u2h2_(Bv.x), yh[0]);
                dB = __hfma2(u2h2_(Bv.y), yh[1], dB);
                dB = __hfma2(u2h2_(Bv.z), yh[2], dB);
                dB = __hfma2(u2h2_(Bv.w), yh[3], dB);

                __half2 m0h = u2h2_(__byte_perm(m01u, 0, 0x1010));
                __half2 m1h = u2h2_(__byte_perm(m01u, 0, 0x3232));
                __half2 dh  = __hfma2(m1h, dB, __hmul2(m0h, dA));

                float2 df = __half22float2(dh);
                pr[i] = df.x + df.y;
            } else {
                pr[i] = 0.0f;
            }
        }

        // Butterfly: reduce 4 values over the 8 lanes of this pixel (fp32).
        float u = hiCol ? pr[0] : pr[2];
        float v = hiCol ? pr[1] : pr[3];
        u = __shfl_xor_sync(0xffffffffu, u, 4);
        v = __shfl_xor_sync(0xffffffffu, v, 4);
        float a  = hiCol ? (pr[2] + u) : (pr[0] + u);
        float bb = hiCol ? (pr[3] + v) : (pr[1] + v);
        bool hi2 = (cg & 2) != 0;
        float t = hi2 ? a : bb;
        t = __shfl_xor_sync(0xffffffffu, t, 2);
        float r = (hi2 ? bb : a) + t;
        r += __shfl_xor_sync(0xffffffffu, r, 1);

        if ((cg & 1) == 0) outp[g * 4 + (cg >> 1)] = r;
    }
}

// ---------------------------------------------------------------------------
extern "C" void kernel_launch(void* const* d_in, const int* in_sizes, int n_in,
                              void* d_out, int out_size)
{
    (void)in_sizes; (void)n_in; (void)out_size;
    const float* x      = (const float*)d_in[0];
    const float* y      = (const float*)d_in[1];
    const float* origin = (const float*)d_in[2];
    const float* focal  = (const float*)d_in[3];
    const float* T12    = (const float*)d_in[4];

    prep_kernel<<<TAB_BLOCKS + CONV_BLOCKS, 256>>>((const float4*)x, origin, focal, T12);

    int nBlocks = (W_ / 8) * (H_ / 4) * B_;   // 15360
    corr_kernel<<<nBlocks, 256>>>((const float4*)y, (float*)d_out);
}